// round 1
// baseline (speedup 1.0000x reference)
#include <cuda_runtime.h>
#include <math.h>

#define NN 100000
#define DD 256
#define HH 256
#define BB 128
#define EE 128
#define NSTEPS 5
#define G4H 1024
#define BH (BB*HH)

// ---------------- scratch (static device globals; no allocations) ----------------
__device__ float g_y1[(size_t)NN*HH];      // FNN intermediate
__device__ float g_hfeat[(size_t)NN*HH];   // FNN output (node features)
__device__ float g_e[NN];                  // attention logits / exp scratch
__device__ float g_gates[BB*G4H];          // LSTM gates
__device__ float g_h[3*BH];
__device__ float g_c[3*BH];
__device__ float g_qstar[BB*2*HH];
__device__ int   g_seg[BB+1];

// ---------------- helpers ----------------
__device__ __forceinline__ float sigf(float x) { return 1.f / (1.f + expf(-x)); }

// ---------------- init ----------------
__global__ void zero_state() {
    int i = blockIdx.x * blockDim.x + threadIdx.x;
    if (i < 3*BH) { g_h[i] = 0.f; g_c[i] = 0.f; }
    if (i < BB*2*HH) g_qstar[i] = 0.f;
}

__global__ void seg_bounds(const int* __restrict__ idx) {
    int b = threadIdx.x;
    if (b > BB) return;
    int lo = 0, hi = NN;
    while (lo < hi) { int mid = (lo + hi) >> 1; if (idx[mid] < b) lo = mid + 1; else hi = mid; }
    g_seg[b] = lo;
}

// ---------------- FNN GEMM: C = act(A @ W + bias), 128x128 tile, BK=16 ----------------
// PHASE 0: A = x (param), C = g_y1, ELU epilogue. PHASE 1: A = g_y1, C = g_hfeat.
template<int PHASE>
__global__ void __launch_bounds__(256, 2)
fnn_gemm(const float* __restrict__ Ax, const float* __restrict__ W,
         const float* __restrict__ bias) {
    const float* A = (PHASE == 0) ? Ax : g_y1;
    float* C = (PHASE == 0) ? g_y1 : g_hfeat;
    __shared__ float As[16*132];   // [k][m], padded stride 132
    __shared__ float Bs[16*128];   // [k][n]
    int tid = threadIdx.x;
    int m0 = blockIdx.x * 128;
    int n0 = blockIdx.y * 128;
    int tx = tid & 15, ty = tid >> 4;
    int c0 = tx * 8, r0 = ty * 8;
    int arow = tid >> 2;           // 0..63
    int akq  = (tid & 3) * 4;      // 0,4,8,12
    int bk   = tid >> 5;           // 0..7
    int bnq  = (tid & 31) * 4;

    float acc[8][8];
    #pragma unroll
    for (int i = 0; i < 8; i++)
        #pragma unroll
        for (int j = 0; j < 8; j++) acc[i][j] = 0.f;

    float4 pa0, pa1, pb0, pb1;
    {
        int gm0 = m0 + arow, gm1 = m0 + arow + 64;
        pa0 = (gm0 < NN) ? *(const float4*)&A[(size_t)gm0*DD + akq] : make_float4(0,0,0,0);
        pa1 = (gm1 < NN) ? *(const float4*)&A[(size_t)gm1*DD + akq] : make_float4(0,0,0,0);
        pb0 = *(const float4*)&W[(size_t)bk*HH + n0 + bnq];
        pb1 = *(const float4*)&W[(size_t)(bk+8)*HH + n0 + bnq];
    }
    for (int kt = 0; kt < DD; kt += 16) {
        As[(akq+0)*132+arow] = pa0.x; As[(akq+1)*132+arow] = pa0.y;
        As[(akq+2)*132+arow] = pa0.z; As[(akq+3)*132+arow] = pa0.w;
        As[(akq+0)*132+arow+64] = pa1.x; As[(akq+1)*132+arow+64] = pa1.y;
        As[(akq+2)*132+arow+64] = pa1.z; As[(akq+3)*132+arow+64] = pa1.w;
        *(float4*)&Bs[bk*128 + bnq]     = pb0;
        *(float4*)&Bs[(bk+8)*128 + bnq] = pb1;
        __syncthreads();
        int kn = kt + 16;
        if (kn < DD) {
            int gm0 = m0 + arow, gm1 = m0 + arow + 64;
            pa0 = (gm0 < NN) ? *(const float4*)&A[(size_t)gm0*DD + kn + akq] : make_float4(0,0,0,0);
            pa1 = (gm1 < NN) ? *(const float4*)&A[(size_t)gm1*DD + kn + akq] : make_float4(0,0,0,0);
            pb0 = *(const float4*)&W[(size_t)(kn+bk)*HH + n0 + bnq];
            pb1 = *(const float4*)&W[(size_t)(kn+bk+8)*HH + n0 + bnq];
        }
        #pragma unroll
        for (int k = 0; k < 16; k++) {
            float a[8], b[8];
            *(float4*)&a[0] = *(const float4*)&As[k*132 + r0];
            *(float4*)&a[4] = *(const float4*)&As[k*132 + r0 + 4];
            *(float4*)&b[0] = *(const float4*)&Bs[k*128 + c0];
            *(float4*)&b[4] = *(const float4*)&Bs[k*128 + c0 + 4];
            #pragma unroll
            for (int i = 0; i < 8; i++)
                #pragma unroll
                for (int j = 0; j < 8; j++)
                    acc[i][j] = fmaf(a[i], b[j], acc[i][j]);
        }
        __syncthreads();
    }
    float bv[8];
    #pragma unroll
    for (int j = 0; j < 8; j++) bv[j] = bias[n0 + c0 + j];
    #pragma unroll
    for (int i = 0; i < 8; i++) {
        int gm = m0 + r0 + i;
        if (gm < NN) {
            float o[8];
            #pragma unroll
            for (int j = 0; j < 8; j++) {
                float v = acc[i][j] + bv[j];
                if (PHASE == 0) v = (v > 0.f) ? v : expm1f(v);
                o[j] = v;
            }
            *(float4*)&C[(size_t)gm*HH + n0 + c0]     = *(float4*)&o[0];
            *(float4*)&C[(size_t)gm*HH + n0 + c0 + 4] = *(float4*)&o[4];
        }
    }
}

// ---------------- LSTM gates: gates = [xin|h] @ [Wih|Whh]^T + bih + bhh ----------------
// out tile 8 (batch) x 64 (gate cols), grid (16, 16) = 256 blocks, 128 threads.
__global__ void __launch_bounds__(128)
lstm_gates(int layer,
           const float* __restrict__ Wih, const float* __restrict__ Whh,
           const float* __restrict__ bih, const float* __restrict__ bhh) {
    __shared__ float As[8*768];     // [r][k], compact stride K
    __shared__ float Ws[32*68];     // [k][j], padded
    const int K1 = (layer == 0) ? 2*HH : HH;
    const int K  = K1 + HH;
    const float* xin = (layer == 0) ? g_qstar : (g_h + (layer-1)*BH);
    const float* hin = g_h + layer*BH;
    int tid = threadIdx.x;
    int b0 = blockIdx.x * 8;
    int n0 = blockIdx.y * 64;
    for (int idx = tid; idx < 8*K; idx += 128) {
        int r = idx / K, k = idx - r*K;
        As[idx] = (k < K1) ? xin[(b0+r)*K1 + k] : hin[(b0+r)*HH + (k - K1)];
    }
    __syncthreads();
    int tx = tid & 15, ty = tid >> 4;   // ty 0..7 -> batch row
    int c0 = tx * 4;
    int wj = tid >> 3;                  // 0..15
    int wk = (tid & 7) * 4;             // 0..28
    float acc[4] = {0.f, 0.f, 0.f, 0.f};
    for (int kt = 0; kt < K; kt += 32) {
        const float* Wsrc; int stride, kc;
        if (kt < K1) { Wsrc = Wih; stride = K1; kc = kt + wk; }
        else         { Wsrc = Whh; stride = HH; kc = kt - K1 + wk; }
        #pragma unroll
        for (int p = 0; p < 4; p++) {
            int j = p*16 + wj;
            float4 v = *(const float4*)&Wsrc[(size_t)(n0+j)*stride + kc];
            Ws[(wk+0)*68+j] = v.x; Ws[(wk+1)*68+j] = v.y;
            Ws[(wk+2)*68+j] = v.z; Ws[(wk+3)*68+j] = v.w;
        }
        __syncthreads();
        const float* arow = As + ty*K + kt;
        #pragma unroll
        for (int k = 0; k < 32; k++) {
            float a = arow[k];
            float4 bv = *(const float4*)&Ws[k*68 + c0];
            acc[0] = fmaf(a, bv.x, acc[0]);
            acc[1] = fmaf(a, bv.y, acc[1]);
            acc[2] = fmaf(a, bv.z, acc[2]);
            acc[3] = fmaf(a, bv.w, acc[3]);
        }
        __syncthreads();
    }
    int gb = b0 + ty;
    #pragma unroll
    for (int j = 0; j < 4; j++) {
        int gc = n0 + c0 + j;
        g_gates[gb*G4H + gc] = acc[j] + bih[gc] + bhh[gc];
    }
}

// ---------------- LSTM cell update (i,f,g,o PyTorch order) ----------------
__global__ void lstm_cell(int layer) {
    int b = blockIdx.x, t = threadIdx.x;
    float* h = g_h + layer*BH;
    float* c = g_c + layer*BH;
    const float* g = g_gates + b*G4H;
    float gi = g[t], gf = g[HH + t], gg = g[2*HH + t], go = g[3*HH + t];
    float cn = sigf(gf) * c[b*HH + t] + sigf(gi) * tanhf(gg);
    float hn = sigf(go) * tanhf(cn);
    c[b*HH + t] = cn;
    h[b*HH + t] = hn;
    if (layer == 2) g_qstar[b*2*HH + t] = hn;   // q part of q_star
}

// ---------------- segment attention: one block per graph segment ----------------
__global__ void __launch_bounds__(256)
attention() {
    __shared__ float q[HH];
    __shared__ float wred[8];
    __shared__ float sred[256];
    __shared__ float s_m;
    int b = blockIdx.x, t = threadIdx.x;
    const float* h2 = g_h + 2*BH;
    q[t] = h2[b*HH + t];
    __syncthreads();
    int s = g_seg[b], e = g_seg[b+1];
    int lane = t & 31, wid = t >> 5;

    // phase 1: e[n] = dot(hfeat[n], q); running max
    float mx = -INFINITY;
    for (int n = s + wid; n < e; n += 8) {
        const float* row = g_hfeat + (size_t)n*HH;
        float sum = 0.f;
        #pragma unroll
        for (int j = 0; j < 8; j++) sum = fmaf(row[lane + j*32], q[lane + j*32], sum);
        #pragma unroll
        for (int o = 16; o > 0; o >>= 1) sum += __shfl_xor_sync(0xffffffffu, sum, o);
        if (lane == 0) g_e[n] = sum;
        mx = fmaxf(mx, sum);
    }
    if (lane == 0) wred[wid] = mx;
    __syncthreads();
    if (t == 0) {
        float m = wred[0];
        #pragma unroll
        for (int w = 1; w < 8; w++) m = fmaxf(m, wred[w]);
        if (!isfinite(m)) m = 0.f;   // empty-segment guard (matches reference)
        s_m = m;
    }
    __syncthreads();
    float m = s_m;

    // phase 2: ex = exp(e - m); denom (deterministic tree reduce)
    float lsum = 0.f;
    for (int n = s + t; n < e; n += 256) {
        float ex = expf(g_e[n] - m);
        g_e[n] = ex;
        lsum += ex;
    }
    sred[t] = lsum;
    __syncthreads();
    for (int st = 128; st > 0; st >>= 1) {
        if (t < st) sred[t] += sred[t + st];
        __syncthreads();
    }
    float den = sred[0] + 1e-16f;

    // phase 3: r[f] = sum_n ex[n] * hfeat[n][f]; thread t owns feature t
    float r0 = 0.f, r1 = 0.f, r2 = 0.f, r3 = 0.f;
    int n = s;
    for (; n + 4 <= e; n += 4) {
        r0 = fmaf(g_e[n],   g_hfeat[(size_t)n*HH + t],     r0);
        r1 = fmaf(g_e[n+1], g_hfeat[(size_t)(n+1)*HH + t], r1);
        r2 = fmaf(g_e[n+2], g_hfeat[(size_t)(n+2)*HH + t], r2);
        r3 = fmaf(g_e[n+3], g_hfeat[(size_t)(n+3)*HH + t], r3);
    }
    for (; n < e; n++) r0 = fmaf(g_e[n], g_hfeat[(size_t)n*HH + t], r0);
    g_qstar[b*2*HH + HH + t] = ((r0 + r1) + (r2 + r3)) / den;
}

// ---------------- output projection: out = q_star @ out_W + out_b ----------------
__global__ void out_proj(const float* __restrict__ W, const float* __restrict__ bvec,
                         float* __restrict__ out) {
    __shared__ float qrow[2*HH];
    int b = blockIdx.x, t = threadIdx.x;    // 128 threads
    #pragma unroll
    for (int i = 0; i < 4; i++) qrow[t + i*128] = g_qstar[b*2*HH + t + i*128];
    __syncthreads();
    float acc = 0.f;
    #pragma unroll 8
    for (int k = 0; k < 2*HH; k++) acc = fmaf(qrow[k], W[k*EE + t], acc);
    out[b*EE + t] = acc + bvec[t];
}

// ---------------- launch ----------------
extern "C" void kernel_launch(void* const* d_in, const int* in_sizes, int n_in,
                              void* d_out, int out_size) {
    const float* x    = (const float*)d_in[0];
    const int*   bidx = (const int*)  d_in[1];
    const float* W1   = (const float*)d_in[2];
    const float* b1   = (const float*)d_in[3];
    const float* W2   = (const float*)d_in[4];
    const float* b2   = (const float*)d_in[5];
    const float* Wih[3] = {(const float*)d_in[6],  (const float*)d_in[10], (const float*)d_in[14]};
    const float* Whh[3] = {(const float*)d_in[7],  (const float*)d_in[11], (const float*)d_in[15]};
    const float* bih[3] = {(const float*)d_in[8],  (const float*)d_in[12], (const float*)d_in[16]};
    const float* bhh[3] = {(const float*)d_in[9],  (const float*)d_in[13], (const float*)d_in[17]};
    const float* outW = (const float*)d_in[18];
    const float* outb = (const float*)d_in[19];
    float* out = (float*)d_out;

    zero_state<<<(3*BH + 255)/256, 256>>>();
    seg_bounds<<<1, 256>>>(bidx);

    dim3 gfnn((NN + 127)/128, HH/128);
    fnn_gemm<0><<<gfnn, 256>>>(x, W1, b1);
    fnn_gemm<1><<<gfnn, 256>>>(x, W2, b2);   // A ignored in phase 1 (reads g_y1)

    dim3 gg(BB/8, G4H/64);
    for (int s = 0; s < NSTEPS; s++) {
        for (int l = 0; l < 3; l++) {
            lstm_gates<<<gg, 128>>>(l, Wih[l], Whh[l], bih[l], bhh[l]);
            lstm_cell<<<BB, HH>>>(l);
        }
        attention<<<BB, 256>>>();
    }
    out_proj<<<BB, EE>>>(outW, outb, out);
}

// round 2
// speedup vs baseline: 1.3828x; 1.3828x over previous
#include <cuda_runtime.h>
#include <math.h>

#define NN 100000
#define DD 256
#define HH 256
#define BB 128
#define EE 128
#define NSTEPS 5
#define G4H 1024
#define BH (BB*HH)
#define NCHUNK 8

typedef unsigned long long ull;

// ---------------- scratch (static device globals; no allocations) ----------------
__device__ float g_y1[(size_t)NN*HH];      // FNN intermediate
__device__ float g_hfeat[(size_t)NN*HH];   // FNN output (node features)
__device__ float g_e[NN];                  // attention logits / exp scratch
__device__ float g_gates[BB*G4H];          // LSTM gates
__device__ float g_h[3*BH];
__device__ float g_c[3*BH];
__device__ float g_qstar[BB*2*HH];
__device__ float g_rpart[BB*NCHUNK*HH];    // partial weighted sums
__device__ float g_denom[BB];
__device__ int   g_seg[BB+1];

// ---------------- helpers ----------------
__device__ __forceinline__ float sigf(float x) { return 1.f / (1.f + expf(-x)); }

__device__ __forceinline__ void ffma2(ull &d, ull a, ull b) {
    asm("fma.rn.f32x2 %0, %1, %2, %3;" : "=l"(d) : "l"(a), "l"(b), "l"(d));
}
__device__ __forceinline__ ull bcast2(float a) {
    ull r;
    asm("mov.b64 %0, {%1, %1};" : "=l"(r) : "f"(a));
    return r;
}
__device__ __forceinline__ void unpack2(ull v, float &x, float &y) {
    asm("mov.b64 {%0, %1}, %2;" : "=f"(x), "=f"(y) : "l"(v));
}

// ---------------- init ----------------
__global__ void zero_state() {
    int i = blockIdx.x * blockDim.x + threadIdx.x;
    if (i < 3*BH) { g_h[i] = 0.f; g_c[i] = 0.f; }
    if (i < BB*2*HH) g_qstar[i] = 0.f;
}

__global__ void seg_bounds(const int* __restrict__ idx) {
    int b = threadIdx.x;
    if (b > BB) return;
    int lo = 0, hi = NN;
    while (lo < hi) { int mid = (lo + hi) >> 1; if (idx[mid] < b) lo = mid + 1; else hi = mid; }
    g_seg[b] = lo;
}

// ---------------- FNN GEMM: C = act(A @ W + bias), 128x128 tile, BK=16, FFMA2 ----------------
template<int PHASE>
__global__ void __launch_bounds__(256, 2)
fnn_gemm(const float* __restrict__ Ax, const float* __restrict__ W,
         const float* __restrict__ bias) {
    const float* A = (PHASE == 0) ? Ax : g_y1;
    float* C = (PHASE == 0) ? g_y1 : g_hfeat;
    __shared__ float As[16*132];   // [k][m], padded stride 132 (132*4 % 16 == 0)
    __shared__ float Bs[16*128];   // [k][n]
    int tid = threadIdx.x;
    int m0 = blockIdx.x * 128;
    int n0 = blockIdx.y * 128;
    int tx = tid & 15, ty = tid >> 4;
    int c0 = tx * 8, r0 = ty * 8;
    int arow = tid >> 2;           // 0..63
    int akq  = (tid & 3) * 4;      // 0,4,8,12
    int bk   = tid >> 5;           // 0..7
    int bnq  = (tid & 31) * 4;

    ull acc[8][4];                 // 8 rows x 4 col-pairs (packed f32x2)
    #pragma unroll
    for (int i = 0; i < 8; i++)
        #pragma unroll
        for (int j = 0; j < 4; j++) acc[i][j] = 0ull;

    float4 pa0, pa1, pb0, pb1;
    {
        int gm0 = m0 + arow, gm1 = m0 + arow + 64;
        pa0 = (gm0 < NN) ? *(const float4*)&A[(size_t)gm0*DD + akq] : make_float4(0,0,0,0);
        pa1 = (gm1 < NN) ? *(const float4*)&A[(size_t)gm1*DD + akq] : make_float4(0,0,0,0);
        pb0 = *(const float4*)&W[(size_t)bk*HH + n0 + bnq];
        pb1 = *(const float4*)&W[(size_t)(bk+8)*HH + n0 + bnq];
    }
    for (int kt = 0; kt < DD; kt += 16) {
        As[(akq+0)*132+arow] = pa0.x; As[(akq+1)*132+arow] = pa0.y;
        As[(akq+2)*132+arow] = pa0.z; As[(akq+3)*132+arow] = pa0.w;
        As[(akq+0)*132+arow+64] = pa1.x; As[(akq+1)*132+arow+64] = pa1.y;
        As[(akq+2)*132+arow+64] = pa1.z; As[(akq+3)*132+arow+64] = pa1.w;
        *(float4*)&Bs[bk*128 + bnq]     = pb0;
        *(float4*)&Bs[(bk+8)*128 + bnq] = pb1;
        __syncthreads();
        int kn = kt + 16;
        if (kn < DD) {
            int gm0 = m0 + arow, gm1 = m0 + arow + 64;
            pa0 = (gm0 < NN) ? *(const float4*)&A[(size_t)gm0*DD + kn + akq] : make_float4(0,0,0,0);
            pa1 = (gm1 < NN) ? *(const float4*)&A[(size_t)gm1*DD + kn + akq] : make_float4(0,0,0,0);
            pb0 = *(const float4*)&W[(size_t)(kn+bk)*HH + n0 + bnq];
            pb1 = *(const float4*)&W[(size_t)(kn+bk+8)*HH + n0 + bnq];
        }
        #pragma unroll
        for (int k = 0; k < 16; k++) {
            float a[8];
            *(float4*)&a[0] = *(const float4*)&As[k*132 + r0];
            *(float4*)&a[4] = *(const float4*)&As[k*132 + r0 + 4];
            ulonglong2 bq0 = *(const ulonglong2*)&Bs[k*128 + c0];
            ulonglong2 bq1 = *(const ulonglong2*)&Bs[k*128 + c0 + 4];
            ull bp0 = bq0.x, bp1 = bq0.y, bp2 = bq1.x, bp3 = bq1.y;
            #pragma unroll
            for (int i = 0; i < 8; i++) {
                ull ap = bcast2(a[i]);
                ffma2(acc[i][0], ap, bp0);
                ffma2(acc[i][1], ap, bp1);
                ffma2(acc[i][2], ap, bp2);
                ffma2(acc[i][3], ap, bp3);
            }
        }
        __syncthreads();
    }
    float bv[8];
    #pragma unroll
    for (int j = 0; j < 8; j++) bv[j] = bias[n0 + c0 + j];
    #pragma unroll
    for (int i = 0; i < 8; i++) {
        int gm = m0 + r0 + i;
        if (gm < NN) {
            float o[8];
            #pragma unroll
            for (int j = 0; j < 4; j++) {
                float x, y;
                unpack2(acc[i][j], x, y);
                float v0 = x + bv[2*j], v1 = y + bv[2*j+1];
                if (PHASE == 0) {
                    v0 = (v0 > 0.f) ? v0 : expm1f(v0);
                    v1 = (v1 > 0.f) ? v1 : expm1f(v1);
                }
                o[2*j] = v0; o[2*j+1] = v1;
            }
            *(float4*)&C[(size_t)gm*HH + n0 + c0]     = *(float4*)&o[0];
            *(float4*)&C[(size_t)gm*HH + n0 + c0 + 4] = *(float4*)&o[4];
        }
    }
}

// ---------------- LSTM gates: gates = [xin|h] @ [Wih|Whh]^T + bih + bhh ----------------
__global__ void __launch_bounds__(128)
lstm_gates(int layer,
           const float* __restrict__ Wih, const float* __restrict__ Whh,
           const float* __restrict__ bih, const float* __restrict__ bhh) {
    __shared__ float As[8*768];     // [r][k], compact stride K
    __shared__ float Ws[32*68];     // [k][j], padded
    const int K1 = (layer == 0) ? 2*HH : HH;
    const int K  = K1 + HH;
    const float* xin = (layer == 0) ? g_qstar : (g_h + (layer-1)*BH);
    const float* hin = g_h + layer*BH;
    int tid = threadIdx.x;
    int b0 = blockIdx.x * 8;
    int n0 = blockIdx.y * 64;
    for (int idx = tid; idx < 8*K; idx += 128) {
        int r = idx / K, k = idx - r*K;
        As[idx] = (k < K1) ? xin[(b0+r)*K1 + k] : hin[(b0+r)*HH + (k - K1)];
    }
    __syncthreads();
    int tx = tid & 15, ty = tid >> 4;   // ty 0..7 -> batch row
    int c0 = tx * 4;
    int wj = tid >> 3;                  // 0..15
    int wk = (tid & 7) * 4;             // 0..28
    float acc[4] = {0.f, 0.f, 0.f, 0.f};
    for (int kt = 0; kt < K; kt += 32) {
        const float* Wsrc; int stride, kc;
        if (kt < K1) { Wsrc = Wih; stride = K1; kc = kt + wk; }
        else         { Wsrc = Whh; stride = HH; kc = kt - K1 + wk; }
        #pragma unroll
        for (int p = 0; p < 4; p++) {
            int j = p*16 + wj;
            float4 v = *(const float4*)&Wsrc[(size_t)(n0+j)*stride + kc];
            Ws[(wk+0)*68+j] = v.x; Ws[(wk+1)*68+j] = v.y;
            Ws[(wk+2)*68+j] = v.z; Ws[(wk+3)*68+j] = v.w;
        }
        __syncthreads();
        const float* arow = As + ty*K + kt;
        #pragma unroll
        for (int k = 0; k < 32; k++) {
            float a = arow[k];
            float4 bv = *(const float4*)&Ws[k*68 + c0];
            acc[0] = fmaf(a, bv.x, acc[0]);
            acc[1] = fmaf(a, bv.y, acc[1]);
            acc[2] = fmaf(a, bv.z, acc[2]);
            acc[3] = fmaf(a, bv.w, acc[3]);
        }
        __syncthreads();
    }
    int gb = b0 + ty;
    #pragma unroll
    for (int j = 0; j < 4; j++) {
        int gc = n0 + c0 + j;
        g_gates[gb*G4H + gc] = acc[j] + bih[gc] + bhh[gc];
    }
}

// ---------------- LSTM cell update (i,f,g,o PyTorch order) ----------------
__global__ void lstm_cell(int layer) {
    int b = blockIdx.x, t = threadIdx.x;
    float* h = g_h + layer*BH;
    float* c = g_c + layer*BH;
    const float* g = g_gates + b*G4H;
    float gi = g[t], gf = g[HH + t], gg = g[2*HH + t], go = g[3*HH + t];
    float cn = sigf(gf) * c[b*HH + t] + sigf(gi) * tanhf(gg);
    float hn = sigf(go) * tanhf(cn);
    c[b*HH + t] = cn;
    h[b*HH + t] = hn;
    if (layer == 2) g_qstar[b*2*HH + t] = hn;   // q part of q_star
}

// ---------------- attention: full-chip parallel over N ----------------
// k1: e[n] = dot(hfeat[n], q[batch_idxs[n]]); one warp per row
__global__ void __launch_bounds__(256)
attn_logits(const int* __restrict__ bidx) {
    int n = blockIdx.x * 8 + (threadIdx.x >> 5);
    if (n >= NN) return;
    int lane = threadIdx.x & 31;
    const float* row = g_hfeat + (size_t)n*HH;
    const float* q = g_h + 2*BH + (size_t)bidx[n]*HH;
    float s = 0.f;
    #pragma unroll
    for (int j = 0; j < 8; j++) s = fmaf(row[lane + 32*j], q[lane + 32*j], s);
    #pragma unroll
    for (int o = 16; o > 0; o >>= 1) s += __shfl_xor_sync(0xffffffffu, s, o);
    if (lane == 0) g_e[n] = s;
}

// k2: per-segment max, exp, sum (deterministic tree reductions)
__global__ void __launch_bounds__(256)
attn_softmax() {
    __shared__ float red[256];
    __shared__ float s_m;
    int b = blockIdx.x, t = threadIdx.x;
    int s = g_seg[b], e = g_seg[b+1];
    float mx = -INFINITY;
    for (int n = s + t; n < e; n += 256) mx = fmaxf(mx, g_e[n]);
    red[t] = mx;
    __syncthreads();
    for (int st = 128; st > 0; st >>= 1) {
        if (t < st) red[t] = fmaxf(red[t], red[t + st]);
        __syncthreads();
    }
    if (t == 0) {
        float m = red[0];
        if (!isfinite(m)) m = 0.f;   // empty-segment guard
        s_m = m;
    }
    __syncthreads();
    float m = s_m;
    float lsum = 0.f;
    for (int n = s + t; n < e; n += 256) {
        float ex = expf(g_e[n] - m);
        g_e[n] = ex;
        lsum += ex;
    }
    __syncthreads();
    red[t] = lsum;
    __syncthreads();
    for (int st = 128; st > 0; st >>= 1) {
        if (t < st) red[t] += red[t + st];
        __syncthreads();
    }
    if (t == 0) g_denom[b] = red[0] + 1e-16f;
}

// k3: partial weighted sums; grid (BB, NCHUNK); thread t owns feature t
__global__ void __launch_bounds__(256)
attn_wsum() {
    int b = blockIdx.x, p = blockIdx.y, t = threadIdx.x;
    int s = g_seg[b], e = g_seg[b+1], len = e - s;
    int c0 = s + (len * p) / NCHUNK;
    int c1 = s + (len * (p+1)) / NCHUNK;
    float r0 = 0.f, r1 = 0.f, r2 = 0.f, r3 = 0.f;
    int n = c0;
    for (; n + 4 <= c1; n += 4) {
        r0 = fmaf(g_e[n],   g_hfeat[(size_t)n*HH + t],     r0);
        r1 = fmaf(g_e[n+1], g_hfeat[(size_t)(n+1)*HH + t], r1);
        r2 = fmaf(g_e[n+2], g_hfeat[(size_t)(n+2)*HH + t], r2);
        r3 = fmaf(g_e[n+3], g_hfeat[(size_t)(n+3)*HH + t], r3);
    }
    for (; n < c1; n++) r0 = fmaf(g_e[n], g_hfeat[(size_t)n*HH + t], r0);
    g_rpart[(size_t)(b*NCHUNK + p)*HH + t] = (r0 + r1) + (r2 + r3);
}

// k4: combine partials -> r part of q_star
__global__ void __launch_bounds__(256)
attn_combine() {
    int b = blockIdx.x, t = threadIdx.x;
    float r = 0.f;
    #pragma unroll
    for (int p = 0; p < NCHUNK; p++) r += g_rpart[(size_t)(b*NCHUNK + p)*HH + t];
    g_qstar[b*2*HH + HH + t] = r / g_denom[b];
}

// ---------------- output projection: out = q_star @ out_W + out_b ----------------
__global__ void out_proj(const float* __restrict__ W, const float* __restrict__ bvec,
                         float* __restrict__ out) {
    __shared__ float qrow[2*HH];
    int b = blockIdx.x, t = threadIdx.x;    // 128 threads
    #pragma unroll
    for (int i = 0; i < 4; i++) qrow[t + i*128] = g_qstar[b*2*HH + t + i*128];
    __syncthreads();
    float acc = 0.f;
    #pragma unroll 8
    for (int k = 0; k < 2*HH; k++) acc = fmaf(qrow[k], W[k*EE + t], acc);
    out[b*EE + t] = acc + bvec[t];
}

// ---------------- launch ----------------
extern "C" void kernel_launch(void* const* d_in, const int* in_sizes, int n_in,
                              void* d_out, int out_size) {
    const float* x    = (const float*)d_in[0];
    const int*   bidx = (const int*)  d_in[1];
    const float* W1   = (const float*)d_in[2];
    const float* b1   = (const float*)d_in[3];
    const float* W2   = (const float*)d_in[4];
    const float* b2   = (const float*)d_in[5];
    const float* Wih[3] = {(const float*)d_in[6],  (const float*)d_in[10], (const float*)d_in[14]};
    const float* Whh[3] = {(const float*)d_in[7],  (const float*)d_in[11], (const float*)d_in[15]};
    const float* bih[3] = {(const float*)d_in[8],  (const float*)d_in[12], (const float*)d_in[16]};
    const float* bhh[3] = {(const float*)d_in[9],  (const float*)d_in[13], (const float*)d_in[17]};
    const float* outW = (const float*)d_in[18];
    const float* outb = (const float*)d_in[19];
    float* out = (float*)d_out;

    zero_state<<<(3*BH + 255)/256, 256>>>();
    seg_bounds<<<1, 256>>>(bidx);

    dim3 gfnn((NN + 127)/128, HH/128);
    fnn_gemm<0><<<gfnn, 256>>>(x, W1, b1);
    fnn_gemm<1><<<gfnn, 256>>>(x, W2, b2);   // A ignored in phase 1 (reads g_y1)

    dim3 gg(BB/8, G4H/64);
    dim3 gw(BB, NCHUNK);
    for (int s = 0; s < NSTEPS; s++) {
        for (int l = 0; l < 3; l++) {
            lstm_gates<<<gg, 128>>>(l, Wih[l], Whh[l], bih[l], bhh[l]);
            lstm_cell<<<BB, HH>>>(l);
        }
        attn_logits<<<(NN + 7)/8, 256>>>(bidx);
        attn_softmax<<<BB, 256>>>();
        attn_wsum<<<gw, 256>>>();
        attn_combine<<<BB, 256>>>();
    }
    out_proj<<<BB, EE>>>(outW, outb, out);
}